// round 11
// baseline (speedup 1.0000x reference)
#include <cuda_runtime.h>
#include <math.h>
#include <math_constants.h>

#ifndef CUDART_INF_F
#define CUDART_INF_F __int_as_float(0x7f800000)
#endif

// ---------------------------------------------------------------------------
// AdaptivePrecisionKVCache: global two-bin min/max reduction + elementwise
// quantize/dequantize.
//   small bin: |x| <= 0.01, levels = 15 ; large bin: |x| > 0.01, levels = 255
//   valid bin <=> bmin < bmax
// R9:
//   - acc_val: 7-op exact accumulator {gmin,gmax,smin,smax,lminAbs} replaces
//     9-op 4-select form. lmin/lmax reconstructed exactly in finalize:
//       lmin = gmin < -T ? gmin : lminAbs
//       lmax = gmax >  T ? gmax : -lminAbs
//     (covers two-sided, one-sided, and empty large-bin cases exactly).
//   - k_reduce back to R3 strided shape (measured best, fewest regs).
//   - finalize separate 1-block kernel (fused version measured -3us in R4/R5).
//   - k_dequant unchanged from R6 (35.2us measured).
// ---------------------------------------------------------------------------

#define THRESH 0.01f
#define RED_BLOCKS 2368          // 148 SMs * 16
#define RED_THREADS 256
#define DQ_THREADS 256
#define DQ_UNROLL 4

__device__ float4 g_partials[RED_BLOCKS];   // gmin, gmax, smin, smax
__device__ float  g_partials_labs[RED_BLOCKS]; // lminAbs
__device__ float4 g_ps;                     // smin, 15/sden, sden/15, svalid
__device__ float4 g_pl;                     // lmin, 255/lden, lden/255, lvalid

struct MM { float gmin, gmax, smin, smax, labs; };

__device__ __forceinline__ void mm_init(MM& m) {
    float inf = CUDART_INF_F;
    m.gmin = inf; m.gmax = -inf; m.smin = inf; m.smax = -inf; m.labs = inf;
}

// 7-op accumulator: 2 plain FMNMX (global), FSETP(|x|>T), @p min |x| (lminAbs),
// @!p min/max (small bin). No FSEL, no BSSY.
__device__ __forceinline__ void acc_val(float x, MM& m) {
    float ax = fabsf(x);
    m.gmin = fminf(m.gmin, x);
    m.gmax = fmaxf(m.gmax, x);
    asm("{\n\t"
        ".reg .pred p;\n\t"
        "setp.gt.f32 p, %3, %4;\n\t"
        "@p  min.f32 %0, %0, %3;\n\t"
        "@!p min.f32 %1, %1, %5;\n\t"
        "@!p max.f32 %2, %2, %5;\n\t"
        "}"
        : "+f"(m.labs), "+f"(m.smin), "+f"(m.smax)
        : "f"(ax), "f"(THRESH), "f"(x));
}

__device__ __forceinline__ void acc_vec(float4 v, MM& m) {
    acc_val(v.x, m); acc_val(v.y, m); acc_val(v.z, m); acc_val(v.w, m);
}

__device__ __forceinline__ void mm_merge(MM& a, const MM& b) {
    a.gmin = fminf(a.gmin, b.gmin);
    a.gmax = fmaxf(a.gmax, b.gmax);
    a.smin = fminf(a.smin, b.smin);
    a.smax = fmaxf(a.smax, b.smax);
    a.labs = fminf(a.labs, b.labs);
}

__device__ __forceinline__ void warp_reduce(MM& m) {
    #pragma unroll
    for (int o = 16; o > 0; o >>= 1) {
        m.gmin = fminf(m.gmin, __shfl_xor_sync(0xffffffffu, m.gmin, o));
        m.gmax = fmaxf(m.gmax, __shfl_xor_sync(0xffffffffu, m.gmax, o));
        m.smin = fminf(m.smin, __shfl_xor_sync(0xffffffffu, m.smin, o));
        m.smax = fmaxf(m.smax, __shfl_xor_sync(0xffffffffu, m.smax, o));
        m.labs = fminf(m.labs, __shfl_xor_sync(0xffffffffu, m.labs, o));
    }
}

__device__ __forceinline__ MM block_reduce(MM m) {
    warp_reduce(m);
    __shared__ MM sm[RED_THREADS / 32];
    int w = threadIdx.x >> 5;
    if ((threadIdx.x & 31) == 0) sm[w] = m;
    __syncthreads();
    MM r = sm[0];
    if (threadIdx.x == 0) {
        #pragma unroll
        for (int i = 1; i < RED_THREADS / 32; i++) mm_merge(r, sm[i]);
    }
    return r;
}

__global__ void __launch_bounds__(RED_THREADS)
k_reduce(const float* __restrict__ in, int n) {
    MM m0, m1, m2, m3;
    mm_init(m0); mm_init(m1); mm_init(m2); mm_init(m3);
    int nvec = n >> 2;
    const float4* __restrict__ in4 = (const float4*)in;
    int S = gridDim.x * blockDim.x;
    int tid = blockIdx.x * blockDim.x + threadIdx.x;
    int i = tid;
    for (; i + 3 * S < nvec; i += 4 * S) {
        float4 v0 = in4[i];
        float4 v1 = in4[i + S];
        float4 v2 = in4[i + 2 * S];
        float4 v3 = in4[i + 3 * S];
        acc_vec(v0, m0); acc_vec(v1, m1); acc_vec(v2, m2); acc_vec(v3, m3);
    }
    for (; i < nvec; i += S) acc_vec(in4[i], m0);
    if (blockIdx.x == 0) {
        for (int j = (nvec << 2) + threadIdx.x; j < n; j += blockDim.x)
            acc_val(in[j], m0);
    }
    mm_merge(m0, m1); mm_merge(m2, m3); mm_merge(m0, m2);
    MM r = block_reduce(m0);
    if (threadIdx.x == 0) {
        g_partials[blockIdx.x] = make_float4(r.gmin, r.gmax, r.smin, r.smax);
        g_partials_labs[blockIdx.x] = r.labs;
    }
}

__global__ void __launch_bounds__(RED_THREADS)
k_finalize() {
    MM m; mm_init(m);
    for (int i = threadIdx.x; i < RED_BLOCKS; i += blockDim.x) {
        float4 p = g_partials[i];
        float la = g_partials_labs[i];
        m.gmin = fminf(m.gmin, p.x);
        m.gmax = fmaxf(m.gmax, p.y);
        m.smin = fminf(m.smin, p.z);
        m.smax = fmaxf(m.smax, p.w);
        m.labs = fminf(m.labs, la);
    }
    MM f = block_reduce(m);
    if (threadIdx.x == 0) {
        // Exact reconstruction of the large bin extrema:
        float lmin = (f.gmin < -THRESH) ? f.gmin : f.labs;
        float lmax = (f.gmax >  THRESH) ? f.gmax : -f.labs;
        bool sv = f.smin < f.smax;
        float sd = sv ? (f.smax - f.smin) : 1.0f;
        g_ps = make_float4(f.smin, 15.0f / sd, sd / 15.0f, sv ? 1.0f : 0.0f);
        bool lv = lmin < lmax;
        float ld = lv ? (lmax - lmin) : 1.0f;
        g_pl = make_float4(lmin, 255.0f / ld, ld / 255.0f, lv ? 1.0f : 0.0f);
    }
}

__device__ __forceinline__ float dq(float x, float4 ps, float4 pl) {
    bool big = fabsf(x) > THRESH;
    float bmin = big ? pl.x : ps.x;
    float sc   = big ? pl.y : ps.y;
    float iv   = big ? pl.z : ps.z;
    float vd   = big ? pl.w : ps.w;
    float q = rintf((x - bmin) * sc);   // rintf == round-half-even == jnp.round
    float d = fmaf(q, iv, bmin);
    return (vd != 0.0f) ? d : x;
}

__device__ __forceinline__ float4 dq4(float4 v, float4 ps, float4 pl) {
    v.x = dq(v.x, ps, pl);
    v.y = dq(v.y, ps, pl);
    v.z = dq(v.z, ps, pl);
    v.w = dq(v.w, ps, pl);
    return v;
}

// Reversed block order (start on the L2-hot tail) + evict-first stores.
__global__ void __launch_bounds__(DQ_THREADS)
k_dequant(const float* __restrict__ in, float* __restrict__ out, int n) {
    const float4 ps = g_ps;
    const float4 pl = g_pl;
    int nvec = n >> 2;
    const float4* __restrict__ in4 = (const float4*)in;
    float4* __restrict__ out4 = (float4*)out;
    int rb = gridDim.x - 1 - blockIdx.x;
    int base = rb * (DQ_UNROLL * DQ_THREADS) + threadIdx.x;

    int idx[DQ_UNROLL];
    float4 v[DQ_UNROLL];
    bool ok[DQ_UNROLL];
    #pragma unroll
    for (int u = 0; u < DQ_UNROLL; u++) {
        idx[u] = base + u * DQ_THREADS;
        ok[u] = idx[u] < nvec;
        if (ok[u]) v[u] = in4[idx[u]];
    }
    #pragma unroll
    for (int u = 0; u < DQ_UNROLL; u++) {
        if (ok[u]) __stcs(&out4[idx[u]], dq4(v[u], ps, pl));
    }
    if (blockIdx.x == 0) {
        for (int j = (nvec << 2) + threadIdx.x; j < n; j += blockDim.x)
            __stcs(&out[j], dq(in[j], ps, pl));
    }
}

extern "C" void kernel_launch(void* const* d_in, const int* in_sizes, int n_in,
                              void* d_out, int out_size) {
    (void)n_in; (void)out_size;
    const float* in = (const float*)d_in[0];
    float* out = (float*)d_out;
    int n = in_sizes[0];

    int nvec = n >> 2;

    k_reduce<<<RED_BLOCKS, RED_THREADS>>>(in, n);
    k_finalize<<<1, RED_THREADS>>>();

    int chunk = DQ_UNROLL * DQ_THREADS;
    int dq_blocks = (nvec + chunk - 1) / chunk;
    if (dq_blocks < 1) dq_blocks = 1;
    k_dequant<<<dq_blocks, DQ_THREADS>>>(in, out, n);
}